// round 7
// baseline (speedup 1.0000x reference)
#include <cuda_runtime.h>
#include <cuda_fp16.h>

// image [8,16,512,512] f32, flow [8,2,512,512] f32, out [8,16,512,512] f32
#define BB 8
#define CC 16
#define HH 512
#define WW 512
#define HWSZ (HH * WW)

// 64 MB fp16 NHWC scratch: record = 16 ch * 2B = 32B per pixel (L2-resident).
__device__ __half g_timg_h[(size_t)BB * HWSZ * CC];

// ---------------------------------------------------------------------------
// Kernel 1: NCHW f32 -> NHWC fp16. Thread-per-pixel.
// Loads: 16 plane reads, warp-coalesced. Stores: 2x STG.128, lane stride 32B.
// ---------------------------------------------------------------------------
__global__ __launch_bounds__(256) void transpose_kernel(
    const float* __restrict__ img)
{
    const int pix = blockIdx.x * 256 + threadIdx.x;
    const int b   = blockIdx.z;

    const float* src = img + (size_t)b * CC * HWSZ + pix;

    float v[CC];
    #pragma unroll
    for (int c = 0; c < CC; ++c)
        v[c] = __ldg(src + (size_t)c * HWSZ);

    __half2 h[8];
    #pragma unroll
    for (int i = 0; i < 8; ++i)
        h[i] = __floats2half2_rn(v[2 * i], v[2 * i + 1]);

    uint4* dst = (uint4*)g_timg_h + ((size_t)b * HWSZ + pix) * 2;
    dst[0] = *(uint4*)&h[0];
    dst[1] = *(uint4*)&h[4];
}

// ---------------------------------------------------------------------------
// Kernel 2: gather, ONE thread per output pixel (32 consecutive pixels/warp).
// 8 independent LDG.128 per thread fetch the 4 corner records (fp16, 32B).
// All 16 output STG.32 are plane-major: each warp store instruction covers
// one full 128B line of one channel plane -> 1 wavefront per instruction.
// ---------------------------------------------------------------------------
__global__ __launch_bounds__(256) void gather_kernel(
    const float* __restrict__ flo,
    float* __restrict__ out)
{
    const int pix = blockIdx.x * 256 + threadIdx.x;
    const int b   = blockIdx.z;
    const int x   = pix & (WW - 1);
    const int y   = pix >> 9;

    const float* flob = flo + (size_t)b * 2 * HWSZ;
    const float gx = (float)x + __ldg(flob + pix);
    const float gy = (float)y + __ldg(flob + HWSZ + pix);

    const float x0f = floorf(gx);
    const float y0f = floorf(gy);
    const float x1f = x0f + 1.0f;
    const float y1f = y0f + 1.0f;

    const float wx1 = gx - x0f, wx0 = 1.0f - wx1;
    const float wy1 = gy - y0f, wy0 = 1.0f - wy1;

    const float vx0 = (x0f >= 0.0f && x0f <= 511.0f) ? 1.0f : 0.0f;
    const float vx1 = (x1f >= 0.0f && x1f <= 511.0f) ? 1.0f : 0.0f;
    const float vy0 = (y0f >= 0.0f && y0f <= 511.0f) ? 1.0f : 0.0f;
    const float vy1 = (y1f >= 0.0f && y1f <= 511.0f) ? 1.0f : 0.0f;

    const float a0 = wx0 * vx0, a1 = wx1 * vx1;
    const float b0 = wy0 * vy0, b1 = wy1 * vy1;

    // mask in the reference's exact op order (f32 throughout)
    const float w00 = a0 * b0, w10 = a1 * b0, w01 = a0 * b1, w11 = a1 * b1;
    const float mask = ((w00 + w10) + w01) + w11;

    float* oc = out + (size_t)b * CC * HWSZ + pix;

    if (mask < 0.9999f) {
        #pragma unroll
        for (int c = 0; c < CC; ++c)
            oc[(size_t)c * HWSZ] = 0.0f;
        return;
    }

    const int xi0 = max((int)x0f, 0), xi1 = min((int)x0f + 1, WW - 1);
    const int yi0 = max((int)y0f, 0), yi1 = min((int)y0f + 1, HH - 1);

    const uint4* recs = (const uint4*)g_timg_h;   // 2 uint4 per pixel record
    const size_t rb = (size_t)b * HWSZ;

    // 8 independent 16B loads: 4 corners x 2 halves (high MLP).
    const size_t r00 = (rb + yi0 * WW + xi0) * 2;
    const size_t r10 = (rb + yi0 * WW + xi1) * 2;
    const size_t r01 = (rb + yi1 * WW + xi0) * 2;
    const size_t r11 = (rb + yi1 * WW + xi1) * 2;

    uint4 c00[2], c10[2], c01[2], c11[2];
    c00[0] = __ldg(recs + r00);     c00[1] = __ldg(recs + r00 + 1);
    c10[0] = __ldg(recs + r10);     c10[1] = __ldg(recs + r10 + 1);
    c01[0] = __ldg(recs + r01);     c01[1] = __ldg(recs + r01 + 1);
    c11[0] = __ldg(recs + r11);     c11[1] = __ldg(recs + r11 + 1);

    const __half2* h00 = (const __half2*)c00;
    const __half2* h10 = (const __half2*)c10;
    const __half2* h01 = (const __half2*)c01;
    const __half2* h11 = (const __half2*)c11;

    #pragma unroll
    for (int q = 0; q < 8; ++q) {   // 8 half2 chunks = 16 channels
        const float2 f00 = __half22float2(h00[q]);
        const float2 f10 = __half22float2(h10[q]);
        const float2 f01 = __half22float2(h01[q]);
        const float2 f11 = __half22float2(h11[q]);

        const float rx = w00 * f00.x + w10 * f10.x + w01 * f01.x + w11 * f11.x;
        const float ry = w00 * f00.y + w10 * f10.y + w01 * f01.y + w11 * f11.y;

        oc[(size_t)(2 * q)     * HWSZ] = rx;
        oc[(size_t)(2 * q + 1) * HWSZ] = ry;
    }
}

extern "C" void kernel_launch(void* const* d_in, const int* in_sizes, int n_in,
                              void* d_out, int out_size)
{
    const float* img = (const float*)d_in[0];
    const float* flo = (const float*)d_in[1];
    float* out = (float*)d_out;

    dim3 gridT(HWSZ / 256, 1, BB);
    transpose_kernel<<<gridT, 256>>>(img);

    dim3 gridG(HWSZ / 256, 1, BB);
    gather_kernel<<<gridG, 256>>>(flo, out);
}

// round 8
// speedup vs baseline: 1.1260x; 1.1260x over previous
#include <cuda_runtime.h>
#include <cuda_fp16.h>

// image [8,16,512,512] f32, flow [8,2,512,512] f32, out [8,16,512,512] f32
#define BB 8
#define CC 16
#define HH 512
#define WW 512
#define HWSZ (HH * WW)

// 64 MB fp16 NHWC scratch: record = 16 ch * 2B = 32B per pixel (L2-resident).
__device__ __half g_timg_h[(size_t)BB * HWSZ * CC];

// ---------------------------------------------------------------------------
// Kernel 1: NCHW f32 -> NHWC fp16. Thread-per-pixel.
// __ldcs plane reads (touch-once), STG.128 stores at 32B lane stride.
// ---------------------------------------------------------------------------
__global__ __launch_bounds__(256) void transpose_kernel(
    const float* __restrict__ img)
{
    const int pix = blockIdx.x * 256 + threadIdx.x;
    const int b   = blockIdx.z;

    const float* src = img + (size_t)b * CC * HWSZ + pix;

    float v[CC];
    #pragma unroll
    for (int c = 0; c < CC; ++c)
        v[c] = __ldcs(src + (size_t)c * HWSZ);

    __half2 h[8];
    #pragma unroll
    for (int i = 0; i < 8; ++i)
        h[i] = __floats2half2_rn(v[2 * i], v[2 * i + 1]);

    uint4* dst = (uint4*)g_timg_h + ((size_t)b * HWSZ + pix) * 2;
    dst[0] = *(uint4*)&h[0];
    dst[1] = *(uint4*)&h[4];
}

// ---------------------------------------------------------------------------
// Kernel 2: gather. Lane = (j = channel quad, g = 4-pixel group).
// Warp covers 32 consecutive pixels; thread owns 4 channels x 4 pixels.
// Loads:  per (pixel, corner) the 4 j-lanes split the 32B record -> 1 line.
// Stores: 4x STG.128 per thread; warp store instr = 4 planes x 1 full line.
// ---------------------------------------------------------------------------
__global__ __launch_bounds__(256) void gather_kernel(
    const float* __restrict__ flo,
    float* __restrict__ out)
{
    const int tid  = threadIdx.x;
    const int lane = tid & 31;
    const int wid  = tid >> 5;
    const int j    = lane & 3;     // channel quad: channels 4j..4j+3
    const int g    = lane >> 2;    // pixel group 0..7

    const int pix0 = (blockIdx.x * 8 + wid) * 32 + g * 4;  // 4-aligned, in-row
    const int b    = blockIdx.z;
    const int x0p  = pix0 & (WW - 1);
    const int yrow = pix0 >> 9;

    const float* flob = flo + (size_t)b * 2 * HWSZ;
    const float4 u = __ldg((const float4*)(flob + pix0));
    const float4 v = __ldg((const float4*)(flob + HWSZ + pix0));
    const float uu[4] = {u.x, u.y, u.z, u.w};
    const float vv[4] = {v.x, v.y, v.z, v.w};

    const uint2* recs = (const uint2*)g_timg_h;   // 4 uint2 per 32B record
    const size_t rb = (size_t)b * HWSZ;

    float acc[4][4];   // [channel-in-quad][pixel]

    #pragma unroll
    for (int p = 0; p < 4; ++p) {
        const float gx = (float)(x0p + p) + uu[p];
        const float gy = (float)yrow + vv[p];

        const float x0f = floorf(gx);
        const float y0f = floorf(gy);
        const float x1f = x0f + 1.0f;
        const float y1f = y0f + 1.0f;

        const float wx1 = gx - x0f, wx0 = 1.0f - wx1;
        const float wy1 = gy - y0f, wy0 = 1.0f - wy1;

        const float vx0 = (x0f >= 0.0f && x0f <= 511.0f) ? 1.0f : 0.0f;
        const float vx1 = (x1f >= 0.0f && x1f <= 511.0f) ? 1.0f : 0.0f;
        const float vy0 = (y0f >= 0.0f && y0f <= 511.0f) ? 1.0f : 0.0f;
        const float vy1 = (y1f >= 0.0f && y1f <= 511.0f) ? 1.0f : 0.0f;

        const float a0 = wx0 * vx0, a1 = wx1 * vx1;
        const float b0 = wy0 * vy0, b1 = wy1 * vy1;

        // mask in the reference's exact op order (f32 throughout)
        const float w00 = a0 * b0, w10 = a1 * b0, w01 = a0 * b1, w11 = a1 * b1;
        const float mask = ((w00 + w10) + w01) + w11;

        if (mask < 0.9999f) {
            acc[0][p] = 0.0f; acc[1][p] = 0.0f;
            acc[2][p] = 0.0f; acc[3][p] = 0.0f;
            continue;
        }

        const int xi0 = max((int)x0f, 0), xi1 = min((int)x0f + 1, WW - 1);
        const int yi0 = max((int)y0f, 0), yi1 = min((int)y0f + 1, HH - 1);

        const uint2 q00 = __ldg(recs + (rb + yi0 * WW + xi0) * 4 + j);
        const uint2 q10 = __ldg(recs + (rb + yi0 * WW + xi1) * 4 + j);
        const uint2 q01 = __ldg(recs + (rb + yi1 * WW + xi0) * 4 + j);
        const uint2 q11 = __ldg(recs + (rb + yi1 * WW + xi1) * 4 + j);

        const __half2* h00 = (const __half2*)&q00;
        const __half2* h10 = (const __half2*)&q10;
        const __half2* h01 = (const __half2*)&q01;
        const __half2* h11 = (const __half2*)&q11;

        #pragma unroll
        for (int q = 0; q < 2; ++q) {   // 2 half2 = 4 channels
            const float2 f00 = __half22float2(h00[q]);
            const float2 f10 = __half22float2(h10[q]);
            const float2 f01 = __half22float2(h01[q]);
            const float2 f11 = __half22float2(h11[q]);
            acc[2 * q + 0][p] = w00 * f00.x + w10 * f10.x + w01 * f01.x + w11 * f11.x;
            acc[2 * q + 1][p] = w00 * f00.y + w10 * f10.y + w01 * f01.y + w11 * f11.y;
        }
    }

    // Stores: channel plane (4j+k), 4 consecutive pixels -> STG.128.
    float* ob = out + (size_t)b * CC * HWSZ + pix0;
    #pragma unroll
    for (int k = 0; k < 4; ++k) {
        const float4 o = make_float4(acc[k][0], acc[k][1], acc[k][2], acc[k][3]);
        __stcs((float4*)(ob + (size_t)(4 * j + k) * HWSZ), o);
    }
}

extern "C" void kernel_launch(void* const* d_in, const int* in_sizes, int n_in,
                              void* d_out, int out_size)
{
    const float* img = (const float*)d_in[0];
    const float* flo = (const float*)d_in[1];
    float* out = (float*)d_out;

    dim3 gridT(HWSZ / 256, 1, BB);
    transpose_kernel<<<gridT, 256>>>(img);

    dim3 gridG(HWSZ / 256, 1, BB);   // block = 8 warps x 32 px = 256 px
    gather_kernel<<<gridG, 256>>>(flo, out);
}